// round 9
// baseline (speedup 1.0000x reference)
#include <cuda_runtime.h>
#include <cuda_bf16.h>
#include <cstdint>

// ---------------------------------------------------------------------------
// DCNv2: B=8, Cin=Cout=256, H=W=64, K=3, S=1, P=1, D=1
// Pipeline (gather FUSED into GEMM):
//   0) wsplit:         weight -> Whi/Wlo (bf16 split), [cout][k], k=c*9+kk
//   1) offset_partial: 8 channel-slices (32 ch) of 3x3 offset conv -> g_om8
//   2) offset_final:   sum + bias, sigmoid mask -> gather records per (kk,m):
//                        g_w4 = {w00,w01,w10,w11} (mask folded, OOB zeroed)
//                        g_o4 = {o00,o01,o10,o11} (clamped element offsets)
//   3) gemm:           B tile computed ON THE FLY (bilinear sample + bf16
//                      hi/lo split -> swizzled SMEM, double-buffered) in the
//                      mma shadow; W via 6-stage cp.async ring; 3-term
//                      compensated bf16 mma.sync (HMMA ceiling bound).
// (tcgen05 unavailable: harness PTX target is compute_103, no 'a' features)
// ---------------------------------------------------------------------------

#define BDIM   8
#define CIN    256
#define COUT   256
#define KKN    9
#define NPIX   4096
#define MTOT   32768
#define KDIM   2304

// ------------------------- scratch (device globals) ------------------------
__device__ float g_om8[8 * 27 * MTOT];            // offset conv partials
__device__ float4 g_w4[KKN * MTOT];               // bilinear weights (masked)
__device__ int4   g_o4[KKN * MTOT];               // tap element offsets
__device__ __nv_bfloat16 g_Whi[COUT * KDIM];      // [n][k]
__device__ __nv_bfloat16 g_Wlo[COUT * KDIM];

// ------------------------- PTX wrappers ------------------------------------
static __device__ __forceinline__ uint32_t smem_u32(const void* p) {
    return (uint32_t)__cvta_generic_to_shared(p);
}
static __device__ __forceinline__ void ldsm_x4(uint32_t& r0, uint32_t& r1,
                                               uint32_t& r2, uint32_t& r3,
                                               uint32_t addr) {
    asm volatile("ldmatrix.sync.aligned.m8n8.x4.shared.b16 {%0,%1,%2,%3}, [%4];"
                 : "=r"(r0), "=r"(r1), "=r"(r2), "=r"(r3) : "r"(addr));
}
static __device__ __forceinline__ void ldsm_x4_t(uint32_t& r0, uint32_t& r1,
                                                 uint32_t& r2, uint32_t& r3,
                                                 uint32_t addr) {
    asm volatile("ldmatrix.sync.aligned.m8n8.x4.trans.shared.b16 {%0,%1,%2,%3}, [%4];"
                 : "=r"(r0), "=r"(r1), "=r"(r2), "=r"(r3) : "r"(addr));
}
static __device__ __forceinline__ void mma_bf16(float* d, const uint32_t* a,
                                                uint32_t b0, uint32_t b1) {
    asm volatile(
        "mma.sync.aligned.m16n8k16.row.col.f32.bf16.bf16.f32 "
        "{%0,%1,%2,%3},{%4,%5,%6,%7},{%8,%9},{%0,%1,%2,%3};"
        : "+f"(d[0]), "+f"(d[1]), "+f"(d[2]), "+f"(d[3])
        : "r"(a[0]), "r"(a[1]), "r"(a[2]), "r"(a[3]), "r"(b0), "r"(b1));
}
static __device__ __forceinline__ void cpasync16(uint32_t dst, const void* src) {
    asm volatile("cp.async.cg.shared.global [%0], [%1], 16;"
                 :: "r"(dst), "l"(src) : "memory");
}
static __device__ __forceinline__ void cp_commit() {
    asm volatile("cp.async.commit_group;" ::: "memory");
}
static __device__ __forceinline__ void cp_wait4() {
    asm volatile("cp.async.wait_group 4;" ::: "memory");
}
static __device__ __forceinline__ void sts128(uint32_t addr, uint4 v) {
    asm volatile("st.shared.v4.b32 [%0], {%1,%2,%3,%4};"
                 :: "r"(addr), "r"(v.x), "r"(v.y), "r"(v.z), "r"(v.w) : "memory");
}

// ===========================================================================
// Kernel 0: weight bf16 hi/lo split
// ===========================================================================
__global__ __launch_bounds__(256) void wsplit_kernel(const float* __restrict__ w)
{
    int i = blockIdx.x * 256 + threadIdx.x;
    if (i < COUT * KDIM) {
        float v = w[i];
        __nv_bfloat16 h = __float2bfloat16(v);
        float hf = __bfloat162float(h);
        g_Whi[i] = h;
        g_Wlo[i] = __float2bfloat16(v - hf);
    }
}

// ===========================================================================
// Kernel 1: offset conv partial (one 32-channel slice per blockIdx.y, 8 total)
// ===========================================================================
__global__ __launch_bounds__(256) void offset_partial_kernel(
    const float* __restrict__ x,
    const float* __restrict__ ow)
{
    const int tid = threadIdx.x;
    const int m   = blockIdx.x * 256 + tid;
    const int sl  = blockIdx.y;                 // slice 0..7
    const int b   = m >> 12;
    const int p   = m & 4095;
    const int ho  = p >> 6;
    const int wo  = p & 63;

    __shared__ __align__(16) float ws[32 * 9 * 28];

    float acc[28];
#pragma unroll
    for (int i = 0; i < 28; i++) acc[i] = 0.f;

    const bool r0ok = (ho > 0), r2ok = (ho < 63);
    const bool c0ok = (wo > 0), c2ok = (wo < 63);

    const int c0 = sl * 32;
    for (int idx = tid; idx < 27 * 32 * 9; idx += 256) {
        int oc  = idx / 288;
        int rem = idx % 288;
        int c   = rem / 9;
        int kk  = rem % 9;
        ws[c * 252 + kk * 28 + oc] = ow[(oc * CIN + c0 + c) * 9 + kk];
    }
    for (int idx = tid; idx < 288; idx += 256) {
        int c = idx / 9, kk = idx % 9;
        ws[c * 252 + kk * 28 + 27] = 0.f;
    }
    __syncthreads();

#pragma unroll 1
    for (int c = 0; c < 32; ++c) {
        const float* xc = x + ((size_t)(b * CIN + c0 + c)) * NPIX;
        float xv[9];
#pragma unroll
        for (int ki = 0; ki < 3; ki++) {
#pragma unroll
            for (int kj = 0; kj < 3; kj++) {
                bool rok = (ki == 0) ? r0ok : ((ki == 2) ? r2ok : true);
                bool cok = (kj == 0) ? c0ok : ((kj == 2) ? c2ok : true);
                int yy = ho - 1 + ki, xx = wo - 1 + kj;
                xv[ki * 3 + kj] = (rok && cok) ? xc[yy * 64 + xx] : 0.f;
            }
        }
#pragma unroll
        for (int kk = 0; kk < 9; kk++) {
            float xvk = xv[kk];
            const float4* wrow =
                reinterpret_cast<const float4*>(&ws[c * 252 + kk * 28]);
#pragma unroll
            for (int o4 = 0; o4 < 7; o4++) {
                float4 w = wrow[o4];
                acc[o4 * 4 + 0] += xvk * w.x;
                acc[o4 * 4 + 1] += xvk * w.y;
                acc[o4 * 4 + 2] += xvk * w.z;
                acc[o4 * 4 + 3] += xvk * w.w;
            }
        }
    }

#pragma unroll
    for (int i = 0; i < 27; i++)
        g_om8[((size_t)(sl * 27 + i)) * MTOT + m] = acc[i];
}

// ===========================================================================
// Kernel 2: offset finalize -> gather records (weights + tap offsets)
// ===========================================================================
__global__ __launch_bounds__(256) void offset_final_kernel(
    const float* __restrict__ ob)
{
    const int m  = blockIdx.x * 256 + threadIdx.x;
    const int ho = (m & 4095) >> 6;
    const int wo = m & 63;

    float acc[27];
#pragma unroll
    for (int i = 0; i < 27; i++) {
        float s = 0.f;
#pragma unroll
        for (int sl = 0; sl < 8; sl++)
            s += g_om8[((size_t)(sl * 27 + i)) * MTOT + m];
        acc[i] = s;
    }

#pragma unroll
    for (int kk = 0; kk < 9; kk++) {
        float dy = acc[2 * kk]     + ob[2 * kk];
        float dx = acc[2 * kk + 1] + ob[2 * kk + 1];
        float mv = acc[18 + kk]    + ob[18 + kk];
        mv = 1.f / (1.f + __expf(-mv));
        int ki = kk / 3, kj = kk % 3;
        float pyv = dy + (float)(ho - 1 + ki);
        float pxv = dx + (float)(wo - 1 + kj);

        float y0f = floorf(pyv), x0f = floorf(pxv);
        float wy1 = pyv - y0f, wx1 = pxv - x0f;
        float wy0 = 1.f - wy1, wx0 = 1.f - wx1;
        int y0 = (int)y0f, x0 = (int)x0f;
        int y1 = y0 + 1,   x1 = x0 + 1;

        float w00 = wy0 * wx0 * mv, w01 = wy0 * wx1 * mv;
        float w10 = wy1 * wx0 * mv, w11 = wy1 * wx1 * mv;
        if (y0 < 0 || y0 > 63) { w00 = 0.f; w01 = 0.f; }
        if (y1 < 0 || y1 > 63) { w10 = 0.f; w11 = 0.f; }
        if (x0 < 0 || x0 > 63) { w00 = 0.f; w10 = 0.f; }
        if (x1 < 0 || x1 > 63) { w01 = 0.f; w11 = 0.f; }

        int y0c = min(max(y0, 0), 63), y1c = min(max(y1, 0), 63);
        int x0c = min(max(x0, 0), 63), x1c = min(max(x1, 0), 63);

        const int idx = kk * MTOT + m;
        g_w4[idx] = make_float4(w00, w01, w10, w11);
        g_o4[idx] = make_int4(y0c * 64 + x0c, y0c * 64 + x1c,
                              y1c * 64 + x0c, y1c * 64 + x1c);
    }
}

// ===========================================================================
// Kernel 3: fused HMMA GEMM  out[cout][m] = sum_k W[cout][k] * sample(k, m)
//   Block tile 128 cout x 128 pixels, 8 warps (warp tile 64x32).
//   W (A op): 6-stage cp.async ring, 128 rows x 80B ([hi32|lo32|pad16]).
//   B op: computed in-kernel. Per stage, thread (bk,bc) samples 8 pixels of
//   k-row bk from x via records, splits to bf16 hi/lo, STS to a 2-buffer
//   swizzled tile (hi 4KB + lo 4KB each). Sampling hides in the mma shadow.
//   Single __syncthreads per stage (covers A ring + B double buffer).
// ===========================================================================
#define NSTG        6
#define A_STG_BYTES 10240
#define A_RING      (NSTG * A_STG_BYTES)      // 61440
#define BBUF_BYTES  8192
#define OFF_BLO     4096
#define GEMM_SMEM   (A_RING + 2 * BBUF_BYTES) // 77824

__global__ __launch_bounds__(256, 1) void gemm_kernel(
    const float* __restrict__ x,
    const float* __restrict__ bias,
    float* __restrict__ out)
{
    extern __shared__ __align__(1024) unsigned char smem[];
    const uint32_t sbase = smem_u32(smem);
    const int tid  = threadIdx.x;
    const int warp = tid >> 5;
    const int lane = tid & 31;
    const int mBase    = blockIdx.x * 128;   // pixel base (one image: 4096%128==0)
    const int coutBase = blockIdx.y * 128;
    const int bimg = mBase >> 12;

    // ------ A (W) staging ------
    const int am = tid >> 1;
    const int ah = tid & 1;
    const char* gA = reinterpret_cast<const char*>(
        (ah ? g_Wlo : g_Whi) + (size_t)(coutBase + am) * KDIM);
    const uint32_t aSts = (uint32_t)(am * 80 + ah * 32);

    // ------ B sampling indices ------
    const int bk = tid >> 4;          // k row in stage 0..15
    const int bc = tid & 15;          // 8-pixel chunk
    const uint32_t bSts = (uint32_t)(bk * 256 + ((bc ^ (bk & 7)) * 16));
    const int recBase = mBase + bc * 8;
    const float* xImg = x + ((size_t)bimg * CIN << 12);

    // ------ fragment addresses ------
    const int wm = (warp >> 2) * 64;
    const int wn = (warp & 3) * 32;
    const uint32_t aAddrBase = sbase +
        (uint32_t)((wm + (lane & 15)) * 80 + ((lane >> 4) & 1) * 16);
    const int kRow   = (lane & 7) + ((lane >> 3) & 1) * 8;
    const int chBase = (wn >> 3) + ((lane >> 4) & 1);
    const uint32_t bOff = (uint32_t)(kRow * 256);
    const uint32_t ch0 = (uint32_t)(((chBase + 0) ^ (kRow & 7)) * 16);
    const uint32_t ch1 = (uint32_t)(((chBase + 2) ^ (kRow & 7)) * 16);

    float acc[4][4][4];
#pragma unroll
    for (int i = 0; i < 4; i++)
#pragma unroll
        for (int j = 0; j < 4; j++)
#pragma unroll
            for (int r = 0; r < 4; r++) acc[i][j][r] = 0.f;

    const int NK = KDIM / 16;   // 144

    auto issueA = [&](int kt, int buf) {
        const uint32_t sb = sbase + (uint32_t)(buf * A_STG_BYTES);
        const char* sa = gA + (size_t)kt * 32;
        cpasync16(sb + aSts,      sa);
        cpasync16(sb + aSts + 16, sa + 16);
        cp_commit();
    };

    // sample stage s into B buffer `buf`
    auto sample = [&](int s, int buf) {
        const int kglob = s * 16 + bk;
        const int c  = kglob / 9;
        const int kk = kglob - c * 9;
        const float* xc = xImg + ((size_t)c << 12);
        const float4* wr = g_w4 + kk * MTOT + recBase;
        const int4*   orr = g_o4 + kk * MTOT + recBase;
        uint4 hp, lp;
        uint32_t hw[8], lw[8];
#pragma unroll
        for (int j = 0; j < 8; j++) {
            float4 w = wr[j];
            int4   o = orr[j];
            float v = w.x * xc[o.x] + w.y * xc[o.y] +
                      w.z * xc[o.z] + w.w * xc[o.w];
            __nv_bfloat16 h = __float2bfloat16(v);
            float hf = __bfloat162float(h);
            __nv_bfloat16 l = __float2bfloat16(v - hf);
            hw[j] = (uint32_t)*reinterpret_cast<unsigned short*>(&h);
            lw[j] = (uint32_t)*reinterpret_cast<unsigned short*>(&l);
        }
        hp.x = hw[0] | (hw[1] << 16); hp.y = hw[2] | (hw[3] << 16);
        hp.z = hw[4] | (hw[5] << 16); hp.w = hw[6] | (hw[7] << 16);
        lp.x = lw[0] | (lw[1] << 16); lp.y = lw[2] | (lw[3] << 16);
        lp.z = lw[4] | (lw[5] << 16); lp.w = lw[6] | (lw[7] << 16);
        const uint32_t bb = sbase + A_RING + (uint32_t)(buf * BBUF_BYTES);
        sts128(bb + bSts,           hp);
        sts128(bb + OFF_BLO + bSts, lp);
    };

    // ---- prologue: 5 A stages in flight, B stage 0 computed ----
#pragma unroll
    for (int kt = 0; kt < 5; ++kt) issueA(kt, kt);
    sample(0, 0);

    for (int kt = 0; kt < NK; ++kt) {
        cp_wait4();
        __syncthreads();   // A stage kt ready; B buf[kt&1] written; old bufs free

        const uint32_t stg = (uint32_t)((kt % NSTG) * A_STG_BYTES);
        const uint32_t bb  = sbase + A_RING + (uint32_t)((kt & 1) * BBUF_BYTES);

        uint32_t ahi[4][4], alo[4][4];
#pragma unroll
        for (int mi = 0; mi < 4; mi++) {
            uint32_t ad = aAddrBase + stg + (uint32_t)(mi * 16 * 80);
            ldsm_x4(ahi[mi][0], ahi[mi][1], ahi[mi][2], ahi[mi][3], ad);
            ldsm_x4(alo[mi][0], alo[mi][1], alo[mi][2], alo[mi][3], ad + 32);
        }
        uint32_t bhi[2][4], blo[2][4];
        {
            const uint32_t hbase = bb + bOff;
            const uint32_t lbase = bb + OFF_BLO + bOff;
            ldsm_x4_t(bhi[0][0], bhi[0][1], bhi[0][2], bhi[0][3], hbase + ch0);
            ldsm_x4_t(bhi[1][0], bhi[1][1], bhi[1][2], bhi[1][3], hbase + ch1);
            ldsm_x4_t(blo[0][0], blo[0][1], blo[0][2], blo[0][3], lbase + ch0);
            ldsm_x4_t(blo[1][0], blo[1][1], blo[1][2], blo[1][3], lbase + ch1);
        }

        if (kt + 5 < NK) issueA(kt + 5, (kt + 5) % NSTG);
        else             cp_commit();   // keep wait_group arithmetic exact

        // ---- 48 mma, term-major; sampling for kt+1 issued in the shadow ----
#pragma unroll
        for (int mi = 0; mi < 4; mi++)
#pragma unroll
            for (int nj = 0; nj < 2; nj++)
#pragma unroll
                for (int h = 0; h < 2; h++)
                    mma_bf16(acc[mi][nj * 2 + h], ahi[mi],
                             bhi[nj][2 * h], bhi[nj][2 * h + 1]);
#pragma unroll
        for (int mi = 0; mi < 4; mi++)
#pragma unroll
            for (int nj = 0; nj < 2; nj++)
#pragma unroll
                for (int h = 0; h < 2; h++)
                    mma_bf16(acc[mi][nj * 2 + h], alo[mi],
                             bhi[nj][2 * h], bhi[nj][2 * h + 1]);
#pragma unroll
        for (int mi = 0; mi < 4; mi++)
#pragma unroll
            for (int nj = 0; nj < 2; nj++)
#pragma unroll
                for (int h = 0; h < 2; h++)
                    mma_bf16(acc[mi][nj * 2 + h], ahi[mi],
                             blo[nj][2 * h], blo[nj][2 * h + 1]);

        if (kt + 1 < NK) sample(kt + 1, (kt + 1) & 1);
    }

    // ---- epilogue ----
    const int g = lane >> 2;
    const int t = lane & 3;
    const int pbB = (mBase & 4095) + wn;
    float* outB = out + (size_t)bimg * COUT * NPIX;

#pragma unroll
    for (int mi = 0; mi < 4; mi++) {
        int c0 = coutBase + wm + mi * 16 + g;
        int c1 = c0 + 8;
        float bv0 = __ldg(&bias[c0]);
        float bv1 = __ldg(&bias[c1]);
        float* r0 = outB + (size_t)c0 * NPIX + pbB;
        float* r1 = outB + (size_t)c1 * NPIX + pbB;
#pragma unroll
        for (int ni = 0; ni < 4; ni++) {
            int pcol = ni * 8 + 2 * t;
            float2 v0 = make_float2(acc[mi][ni][0] + bv0, acc[mi][ni][1] + bv0);
            float2 v1 = make_float2(acc[mi][ni][2] + bv1, acc[mi][ni][3] + bv1);
            *reinterpret_cast<float2*>(r0 + pcol) = v0;
            *reinterpret_cast<float2*>(r1 + pcol) = v1;
        }
    }
}

// ===========================================================================
extern "C" void kernel_launch(void* const* d_in, const int* in_sizes, int n_in,
                              void* d_out, int out_size)
{
    const float* x        = (const float*)d_in[0];
    const float* weight   = (const float*)d_in[1];
    const float* bias     = (const float*)d_in[2];
    const float* offset_w = (const float*)d_in[3];
    const float* offset_b = (const float*)d_in[4];
    float* out = (float*)d_out;

    cudaFuncSetAttribute(gemm_kernel,
                         cudaFuncAttributeMaxDynamicSharedMemorySize, GEMM_SMEM);

    // 0) weight hi/lo split
    wsplit_kernel<<<(COUT * KDIM + 255) / 256, 256>>>(weight);

    // 1) offset conv partials (8 channel slices of 32)
    dim3 ogrid(MTOT / 256, 8);
    offset_partial_kernel<<<ogrid, 256>>>(x, offset_w);

    // 2) finalize offsets -> gather records
    offset_final_kernel<<<MTOT / 256, 256>>>(offset_b);

    // 3) fused gather + HMMA GEMM + bias
    dim3 mgrid(MTOT / 128, COUT / 128);
    gemm_kernel<<<mgrid, 256, GEMM_SMEM>>>(x, bias, out);
}

// round 10
// speedup vs baseline: 3.7517x; 3.7517x over previous
#include <cuda_runtime.h>
#include <cuda_fp16.h>
#include <cstdint>

// ---------------------------------------------------------------------------
// DCNv2: B=8, Cin=Cout=256, H=W=64, K=3, S=1, P=1, D=1
// Pipeline (R8 structure, fp16 2-term GEMM):
//   0) wsplit:         weight -> Whi/Wlo (fp16 split), [cout][k]
//   1) offset_partial: 8 channel-slices (32 ch) of 3x3 offset conv -> g_om8
//   2) offset_final:   sum + bias, sigmoid mask, sampling positions
//   3) gather:         bilinear sample * mask -> A fp16 (single), K-major [k][m]
//   4) gemm:           mma.sync m16n8k16 f16, 2-term split acc += A*Whi + A*Wlo
//                      cp.async 6-stage pipeline, term-major mma order
// Error budget: A fp16 rounding 2^-12 dominates -> rel_err ~2.4e-4 (<1e-3).
// (tcgen05 unavailable: harness PTX target is compute_103, no 'a' features.
//  R9 lesson: fused gather at 1 CTA/SM exposes scattered-LDG latency; don't.)
// ---------------------------------------------------------------------------

#define BDIM   8
#define CIN    256
#define COUT   256
#define KKN    9
#define NPIX   4096
#define MTOT   32768
#define KDIM   2304

// ------------------------- scratch (device globals) ------------------------
__device__ float g_py[BDIM * KKN * NPIX];
__device__ float g_px[BDIM * KKN * NPIX];
__device__ float g_pm[BDIM * KKN * NPIX];
__device__ float g_om8[8 * 27 * MTOT];
__device__ __half g_Ah[(size_t)KDIM * MTOT];     // [k][m]  (151 MB)
__device__ __half g_Whi[COUT * KDIM];            // [n][k]
__device__ __half g_Wlo[COUT * KDIM];

// ------------------------- PTX wrappers ------------------------------------
static __device__ __forceinline__ uint32_t smem_u32(const void* p) {
    return (uint32_t)__cvta_generic_to_shared(p);
}
static __device__ __forceinline__ void ldsm_x4(uint32_t& r0, uint32_t& r1,
                                               uint32_t& r2, uint32_t& r3,
                                               uint32_t addr) {
    asm volatile("ldmatrix.sync.aligned.m8n8.x4.shared.b16 {%0,%1,%2,%3}, [%4];"
                 : "=r"(r0), "=r"(r1), "=r"(r2), "=r"(r3) : "r"(addr));
}
static __device__ __forceinline__ void ldsm_x4_t(uint32_t& r0, uint32_t& r1,
                                                 uint32_t& r2, uint32_t& r3,
                                                 uint32_t addr) {
    asm volatile("ldmatrix.sync.aligned.m8n8.x4.trans.shared.b16 {%0,%1,%2,%3}, [%4];"
                 : "=r"(r0), "=r"(r1), "=r"(r2), "=r"(r3) : "r"(addr));
}
static __device__ __forceinline__ void mma_f16(float* d, const uint32_t* a,
                                               uint32_t b0, uint32_t b1) {
    asm volatile(
        "mma.sync.aligned.m16n8k16.row.col.f32.f16.f16.f32 "
        "{%0,%1,%2,%3},{%4,%5,%6,%7},{%8,%9},{%0,%1,%2,%3};"
        : "+f"(d[0]), "+f"(d[1]), "+f"(d[2]), "+f"(d[3])
        : "r"(a[0]), "r"(a[1]), "r"(a[2]), "r"(a[3]), "r"(b0), "r"(b1));
}
static __device__ __forceinline__ void cpasync16(uint32_t dst, const void* src) {
    asm volatile("cp.async.cg.shared.global [%0], [%1], 16;"
                 :: "r"(dst), "l"(src) : "memory");
}
static __device__ __forceinline__ void cp_commit() {
    asm volatile("cp.async.commit_group;" ::: "memory");
}
static __device__ __forceinline__ void cp_wait4() {
    asm volatile("cp.async.wait_group 4;" ::: "memory");
}

// ===========================================================================
// Kernel 0: weight fp16 hi/lo split
// ===========================================================================
__global__ __launch_bounds__(256) void wsplit_kernel(const float* __restrict__ w)
{
    int i = blockIdx.x * 256 + threadIdx.x;
    if (i < COUT * KDIM) {
        float v = w[i];
        __half h = __float2half_rn(v);
        float hf = __half2float(h);
        g_Whi[i] = h;
        g_Wlo[i] = __float2half_rn(v - hf);
    }
}

// ===========================================================================
// Kernel 1: offset conv partial (one 32-channel slice per blockIdx.y, 8 total)
// ===========================================================================
__global__ __launch_bounds__(256) void offset_partial_kernel(
    const float* __restrict__ x,
    const float* __restrict__ ow)
{
    const int tid = threadIdx.x;
    const int m   = blockIdx.x * 256 + tid;
    const int sl  = blockIdx.y;                 // slice 0..7
    const int b   = m >> 12;
    const int p   = m & 4095;
    const int ho  = p >> 6;
    const int wo  = p & 63;

    __shared__ __align__(16) float ws[32 * 9 * 28];

    float acc[28];
#pragma unroll
    for (int i = 0; i < 28; i++) acc[i] = 0.f;

    const bool r0ok = (ho > 0), r2ok = (ho < 63);
    const bool c0ok = (wo > 0), c2ok = (wo < 63);

    const int c0 = sl * 32;
    for (int idx = tid; idx < 27 * 32 * 9; idx += 256) {
        int oc  = idx / 288;
        int rem = idx % 288;
        int c   = rem / 9;
        int kk  = rem % 9;
        ws[c * 252 + kk * 28 + oc] = ow[(oc * CIN + c0 + c) * 9 + kk];
    }
    for (int idx = tid; idx < 288; idx += 256) {
        int c = idx / 9, kk = idx % 9;
        ws[c * 252 + kk * 28 + 27] = 0.f;
    }
    __syncthreads();

#pragma unroll 1
    for (int c = 0; c < 32; ++c) {
        const float* xc = x + ((size_t)(b * CIN + c0 + c)) * NPIX;
        float xv[9];
#pragma unroll
        for (int ki = 0; ki < 3; ki++) {
#pragma unroll
            for (int kj = 0; kj < 3; kj++) {
                bool rok = (ki == 0) ? r0ok : ((ki == 2) ? r2ok : true);
                bool cok = (kj == 0) ? c0ok : ((kj == 2) ? c2ok : true);
                int yy = ho - 1 + ki, xx = wo - 1 + kj;
                xv[ki * 3 + kj] = (rok && cok) ? xc[yy * 64 + xx] : 0.f;
            }
        }
#pragma unroll
        for (int kk = 0; kk < 9; kk++) {
            float xvk = xv[kk];
            const float4* wrow =
                reinterpret_cast<const float4*>(&ws[c * 252 + kk * 28]);
#pragma unroll
            for (int o4 = 0; o4 < 7; o4++) {
                float4 w = wrow[o4];
                acc[o4 * 4 + 0] += xvk * w.x;
                acc[o4 * 4 + 1] += xvk * w.y;
                acc[o4 * 4 + 2] += xvk * w.z;
                acc[o4 * 4 + 3] += xvk * w.w;
            }
        }
    }

#pragma unroll
    for (int i = 0; i < 27; i++)
        g_om8[((size_t)(sl * 27 + i)) * MTOT + m] = acc[i];
}

// ===========================================================================
// Kernel 2: offset finalize -> py / px / mask  (sums 8 slices)
// ===========================================================================
__global__ __launch_bounds__(256) void offset_final_kernel(
    const float* __restrict__ ob)
{
    const int m  = blockIdx.x * 256 + threadIdx.x;
    const int b  = m >> 12;
    const int p  = m & 4095;
    const int ho = p >> 6;
    const int wo = p & 63;

    float acc[27];
#pragma unroll
    for (int i = 0; i < 27; i++) {
        float s = 0.f;
#pragma unroll
        for (int sl = 0; sl < 8; sl++)
            s += g_om8[((size_t)(sl * 27 + i)) * MTOT + m];
        acc[i] = s;
    }

#pragma unroll
    for (int kk = 0; kk < 9; kk++) {
        float dy = acc[2 * kk]     + ob[2 * kk];
        float dx = acc[2 * kk + 1] + ob[2 * kk + 1];
        float mv = acc[18 + kk]    + ob[18 + kk];
        mv = 1.f / (1.f + __expf(-mv));
        int ki = kk / 3, kj = kk % 3;
        float pyv = dy + (float)(ho - 1 + ki);
        float pxv = dx + (float)(wo - 1 + kj);
        int o = ((b * 9 + kk) << 12) + p;
        g_py[o] = pyv;
        g_px[o] = pxv;
        g_pm[o] = mv;
    }
}

// ===========================================================================
// Kernel 3: bilinear gather -> A fp16, K-major g_Ah[k = c*9+kk][m]
//   c-split: blockIdx.z in {0,1}, 128 channels each
// ===========================================================================
__global__ __launch_bounds__(256) void gather_kernel(const float* __restrict__ x)
{
    const int tid = threadIdx.x;
    const int m   = blockIdx.x * 256 + tid;
    const int kk  = blockIdx.y;
    const int cs  = blockIdx.z * 128;
    const int b   = m >> 12;
    const int p   = m & 4095;

    const int o = ((b * 9 + kk) << 12) + p;
    const float pyv = g_py[o];
    const float pxv = g_px[o];
    const float mv  = g_pm[o];

    float y0f = floorf(pyv), x0f = floorf(pxv);
    float wy1 = pyv - y0f, wx1 = pxv - x0f;
    float wy0 = 1.f - wy1, wx0 = 1.f - wx1;
    int y0 = (int)y0f, x0 = (int)x0f;
    int y1 = y0 + 1,   x1 = x0 + 1;

    float w00 = wy0 * wx0 * mv, w01 = wy0 * wx1 * mv;
    float w10 = wy1 * wx0 * mv, w11 = wy1 * wx1 * mv;
    if (y0 < 0 || y0 > 63) { w00 = 0.f; w01 = 0.f; }
    if (y1 < 0 || y1 > 63) { w10 = 0.f; w11 = 0.f; }
    if (x0 < 0 || x0 > 63) { w00 = 0.f; w10 = 0.f; }
    if (x1 < 0 || x1 > 63) { w01 = 0.f; w11 = 0.f; }

    int y0c = min(max(y0, 0), 63), y1c = min(max(y1, 0), 63);
    int x0c = min(max(x0, 0), 63), x1c = min(max(x1, 0), 63);
    const int o00 = y0c * 64 + x0c, o01 = y0c * 64 + x1c;
    const int o10 = y1c * 64 + x0c, o11 = y1c * 64 + x1c;

    const float* xb = x + (size_t)(b * CIN + cs) * NPIX;
    const size_t base = (size_t)kk * MTOT + m + (size_t)cs * 9 * MTOT;

#pragma unroll 8
    for (int c = 0; c < 128; ++c) {
        const float* xc = xb + (size_t)c * NPIX;
        float v = w00 * xc[o00] + w01 * xc[o01] +
                  w10 * xc[o10] + w11 * xc[o11];
        g_Ah[base + (size_t)c * 9 * MTOT] = __float2half_rn(v);
    }
}

// ===========================================================================
// Kernel 4: HMMA GEMM  out[cout][m] = sum_k W[cout][k] * A[k][m]
//   Block tile 128 cout x 128 pixels, 8 warps (warp tile 64x32).
//   6-stage cp.async ring (BK=16, 14.3 KB/stage), one barrier per stage.
//   32 mma per warp per stage, 2-term: acc += Whi*A ; acc += Wlo*A.
//   Stage layout: [Ws 128x80 ([hi32|lo32|pad16]) | As 16x256 swizzled]
// ===========================================================================
#define NSTG      6
#define STG_BYTES 14336
#define OFF_B     10240
#define GEMM_SMEM (NSTG * STG_BYTES)   // 86016

__global__ __launch_bounds__(256, 1) void gemm_kernel(
    const float* __restrict__ bias,
    float* __restrict__ out)
{
    extern __shared__ __align__(1024) unsigned char smem[];
    const uint32_t sbase = smem_u32(smem);
    const int tid  = threadIdx.x;
    const int warp = tid >> 5;
    const int lane = tid & 31;
    const int mBase    = blockIdx.x * 128;   // pixel base
    const int coutBase = blockIdx.y * 128;

    // ------ staging indices ------
    const int am = tid >> 1;          // W: cout row in tile 0..127
    const int ah = tid & 1;           // W: 0=hi, 1=lo
    const int bk = tid >> 4;          // A: k row 0..15
    const int bc = tid & 15;          // A: pixel chunk (8 fp16)

    const char* gW = reinterpret_cast<const char*>(
        (ah ? g_Wlo : g_Whi) + (size_t)(coutBase + am) * KDIM);
    const char* gB = reinterpret_cast<const char*>(
        g_Ah + (size_t)bk * MTOT + mBase + bc * 8);

    const uint32_t aSts = (uint32_t)(am * 80 + ah * 32);
    const uint32_t bSts = (uint32_t)(bk * 256 + ((bc ^ (bk & 7)) * 16));

    // ------ fragment addresses ------
    const int wm = (warp >> 2) * 64;
    const int wn = (warp & 3) * 32;
    const uint32_t aAddrBase = sbase +
        (uint32_t)((wm + (lane & 15)) * 80 + ((lane >> 4) & 1) * 16);
    const int kRow   = (lane & 7) + ((lane >> 3) & 1) * 8;
    const int chBase = (wn >> 3) + ((lane >> 4) & 1);
    const uint32_t bOff = (uint32_t)(kRow * 256);
    const uint32_t ch0 = (uint32_t)(((chBase + 0) ^ (kRow & 7)) * 16);
    const uint32_t ch1 = (uint32_t)(((chBase + 2) ^ (kRow & 7)) * 16);

    float acc[4][4][4];
#pragma unroll
    for (int i = 0; i < 4; i++)
#pragma unroll
        for (int j = 0; j < 4; j++)
#pragma unroll
            for (int r = 0; r < 4; r++) acc[i][j][r] = 0.f;

    const int NK = KDIM / 16;   // 144

    auto issue = [&](int kt, int buf) {
        const uint32_t sb = sbase + (uint32_t)(buf * STG_BYTES);
        const char* sw = gW + (size_t)kt * 32;
        const char* sb2 = gB + (size_t)kt * 16 * MTOT * 2;
        cpasync16(sb + aSts,         sw);
        cpasync16(sb + aSts + 16,    sw + 16);
        cpasync16(sb + OFF_B + bSts, sb2);
        cp_commit();
    };

#pragma unroll
    for (int kt = 0; kt < 5; ++kt) issue(kt, kt);

    for (int kt = 0; kt < NK; ++kt) {
        const int buf = kt % NSTG;
        cp_wait4();
        __syncthreads();

        const uint32_t stg = (uint32_t)(buf * STG_BYTES);

        uint32_t whi[4][4], wlo[4][4];
#pragma unroll
        for (int mi = 0; mi < 4; mi++) {
            uint32_t ad = aAddrBase + stg + (uint32_t)(mi * 16 * 80);
            ldsm_x4(whi[mi][0], whi[mi][1], whi[mi][2], whi[mi][3], ad);
            ldsm_x4(wlo[mi][0], wlo[mi][1], wlo[mi][2], wlo[mi][3], ad + 32);
        }
        uint32_t bfr[2][4];
        {
            const uint32_t hbase = sbase + OFF_B + stg + bOff;
            ldsm_x4_t(bfr[0][0], bfr[0][1], bfr[0][2], bfr[0][3], hbase + ch0);
            ldsm_x4_t(bfr[1][0], bfr[1][1], bfr[1][2], bfr[1][3], hbase + ch1);
        }

        if (kt + 5 < NK) issue(kt + 5, (kt + 5) % NSTG);
        else             cp_commit();

        // ---- 32 mma, term-major (16 independent accumulators per sweep) ----
#pragma unroll
        for (int mi = 0; mi < 4; mi++)
#pragma unroll
            for (int nj = 0; nj < 2; nj++)
#pragma unroll
                for (int h = 0; h < 2; h++)
                    mma_f16(acc[mi][nj * 2 + h], whi[mi],
                            bfr[nj][2 * h], bfr[nj][2 * h + 1]);
#pragma unroll
        for (int mi = 0; mi < 4; mi++)
#pragma unroll
            for (int nj = 0; nj < 2; nj++)
#pragma unroll
                for (int h = 0; h < 2; h++)
                    mma_f16(acc[mi][nj * 2 + h], wlo[mi],
                            bfr[nj][2 * h], bfr[nj][2 * h + 1]);

        __syncthreads();
    }

    // ---- epilogue ----
    const int g = lane >> 2;
    const int t = lane & 3;
    const int b    = mBase >> 12;
    const int pbB  = (mBase & 4095) + wn;
    float* outB = out + (size_t)b * COUT * NPIX;

#pragma unroll
    for (int mi = 0; mi < 4; mi++) {
        int c0 = coutBase + wm + mi * 16 + g;
        int c1 = c0 + 8;
        float bv0 = __ldg(&bias[c0]);
        float bv1 = __ldg(&bias[c1]);
        float* r0 = outB + (size_t)c0 * NPIX + pbB;
        float* r1 = outB + (size_t)c1 * NPIX + pbB;
#pragma unroll
        for (int ni = 0; ni < 4; ni++) {
            int pcol = ni * 8 + 2 * t;
            float2 v0 = make_float2(acc[mi][ni][0] + bv0, acc[mi][ni][1] + bv0);
            float2 v1 = make_float2(acc[mi][ni][2] + bv1, acc[mi][ni][3] + bv1);
            *reinterpret_cast<float2*>(r0 + pcol) = v0;
            *reinterpret_cast<float2*>(r1 + pcol) = v1;
        }
    }
}

// ===========================================================================
extern "C" void kernel_launch(void* const* d_in, const int* in_sizes, int n_in,
                              void* d_out, int out_size)
{
    const float* x        = (const float*)d_in[0];
    const float* weight   = (const float*)d_in[1];
    const float* bias     = (const float*)d_in[2];
    const float* offset_w = (const float*)d_in[3];
    const float* offset_b = (const float*)d_in[4];
    float* out = (float*)d_out;

    cudaFuncSetAttribute(gemm_kernel,
                         cudaFuncAttributeMaxDynamicSharedMemorySize, GEMM_SMEM);

    // 0) weight fp16 hi/lo split
    wsplit_kernel<<<(COUT * KDIM + 255) / 256, 256>>>(weight);

    // 1) offset conv partials (8 channel slices of 32)
    dim3 ogrid(MTOT / 256, 8);
    offset_partial_kernel<<<ogrid, 256>>>(x, offset_w);

    // 2) finalize offsets
    offset_final_kernel<<<MTOT / 256, 256>>>(offset_b);

    // 3) bilinear gather -> fp16 A matrix (c-split x2)
    dim3 ggrid(MTOT / 256, KKN, 2);
    gather_kernel<<<ggrid, 256>>>(x);

    // 4) HMMA GEMM + bias (cp.async pipelined, 2-term fp16)
    dim3 mgrid(MTOT / 128, COUT / 128);
    gemm_kernel<<<mgrid, 256, GEMM_SMEM>>>(bias, out);
}

// round 11
// speedup vs baseline: 4.8131x; 1.2829x over previous
#include <cuda_runtime.h>
#include <cuda_fp16.h>
#include <cstdint>

// ---------------------------------------------------------------------------
// DCNv2: B=8, Cin=Cout=256, H=W=64, K=3, S=1, P=1, D=1
// Pipeline (single-fp16 GEMM):
//   0) wconv:          weight -> fp16, [cout][k]
//   1) offset_partial: 8 channel-slices (32 ch) of 3x3 offset conv -> g_om8
//   2) offset_final:   sum + bias, sigmoid mask, sampling positions
//   3) gather:         bilinear sample * mask -> A fp16, K-major [k][m]
//   4) gemm:           mma.sync m16n8k16 f16 (single term), cp.async 6-stage
// Error budget: A + W fp16 rounding -> rel_err ~2.9e-4 (<1e-3; calibrated
// model: A-only measured 2.07e-4 in R10).
// (tcgen05 unavailable: harness PTX targets compute_103, no 'a' features.
//  R9 lesson: fused gather at 1 CTA/SM exposes scattered-LDG latency; don't.)
// ---------------------------------------------------------------------------

#define BDIM   8
#define CIN    256
#define COUT   256
#define KKN    9
#define NPIX   4096
#define MTOT   32768
#define KDIM   2304

// ------------------------- scratch (device globals) ------------------------
__device__ float g_py[BDIM * KKN * NPIX];
__device__ float g_px[BDIM * KKN * NPIX];
__device__ float g_pm[BDIM * KKN * NPIX];
__device__ float g_om8[8 * 27 * MTOT];
__device__ __half g_Ah[(size_t)KDIM * MTOT];     // [k][m]  (151 MB)
__device__ __half g_Wh[COUT * KDIM];             // [n][k]

// ------------------------- PTX wrappers ------------------------------------
static __device__ __forceinline__ uint32_t smem_u32(const void* p) {
    return (uint32_t)__cvta_generic_to_shared(p);
}
static __device__ __forceinline__ void ldsm_x4(uint32_t& r0, uint32_t& r1,
                                               uint32_t& r2, uint32_t& r3,
                                               uint32_t addr) {
    asm volatile("ldmatrix.sync.aligned.m8n8.x4.shared.b16 {%0,%1,%2,%3}, [%4];"
                 : "=r"(r0), "=r"(r1), "=r"(r2), "=r"(r3) : "r"(addr));
}
static __device__ __forceinline__ void ldsm_x4_t(uint32_t& r0, uint32_t& r1,
                                                 uint32_t& r2, uint32_t& r3,
                                                 uint32_t addr) {
    asm volatile("ldmatrix.sync.aligned.m8n8.x4.trans.shared.b16 {%0,%1,%2,%3}, [%4];"
                 : "=r"(r0), "=r"(r1), "=r"(r2), "=r"(r3) : "r"(addr));
}
static __device__ __forceinline__ void mma_f16(float* d, const uint32_t* a,
                                               uint32_t b0, uint32_t b1) {
    asm volatile(
        "mma.sync.aligned.m16n8k16.row.col.f32.f16.f16.f32 "
        "{%0,%1,%2,%3},{%4,%5,%6,%7},{%8,%9},{%0,%1,%2,%3};"
        : "+f"(d[0]), "+f"(d[1]), "+f"(d[2]), "+f"(d[3])
        : "r"(a[0]), "r"(a[1]), "r"(a[2]), "r"(a[3]), "r"(b0), "r"(b1));
}
static __device__ __forceinline__ void cpasync16(uint32_t dst, const void* src) {
    asm volatile("cp.async.cg.shared.global [%0], [%1], 16;"
                 :: "r"(dst), "l"(src) : "memory");
}
static __device__ __forceinline__ void cp_commit() {
    asm volatile("cp.async.commit_group;" ::: "memory");
}
static __device__ __forceinline__ void cp_wait4() {
    asm volatile("cp.async.wait_group 4;" ::: "memory");
}

// ===========================================================================
// Kernel 0: weight -> fp16
// ===========================================================================
__global__ __launch_bounds__(256) void wconv_kernel(const float* __restrict__ w)
{
    int i = blockIdx.x * 256 + threadIdx.x;
    if (i < COUT * KDIM)
        g_Wh[i] = __float2half_rn(w[i]);
}

// ===========================================================================
// Kernel 1: offset conv partial (one 32-channel slice per blockIdx.y, 8 total)
// ===========================================================================
__global__ __launch_bounds__(256) void offset_partial_kernel(
    const float* __restrict__ x,
    const float* __restrict__ ow)
{
    const int tid = threadIdx.x;
    const int m   = blockIdx.x * 256 + tid;
    const int sl  = blockIdx.y;                 // slice 0..7
    const int b   = m >> 12;
    const int p   = m & 4095;
    const int ho  = p >> 6;
    const int wo  = p & 63;

    __shared__ __align__(16) float ws[32 * 9 * 28];

    float acc[28];
#pragma unroll
    for (int i = 0; i < 28; i++) acc[i] = 0.f;

    const bool r0ok = (ho > 0), r2ok = (ho < 63);
    const bool c0ok = (wo > 0), c2ok = (wo < 63);

    const int c0 = sl * 32;
    for (int idx = tid; idx < 27 * 32 * 9; idx += 256) {
        int oc  = idx / 288;
        int rem = idx % 288;
        int c   = rem / 9;
        int kk  = rem % 9;
        ws[c * 252 + kk * 28 + oc] = ow[(oc * CIN + c0 + c) * 9 + kk];
    }
    for (int idx = tid; idx < 288; idx += 256) {
        int c = idx / 9, kk = idx % 9;
        ws[c * 252 + kk * 28 + 27] = 0.f;
    }
    __syncthreads();

#pragma unroll 1
    for (int c = 0; c < 32; ++c) {
        const float* xc = x + ((size_t)(b * CIN + c0 + c)) * NPIX;
        float xv[9];
#pragma unroll
        for (int ki = 0; ki < 3; ki++) {
#pragma unroll
            for (int kj = 0; kj < 3; kj++) {
                bool rok = (ki == 0) ? r0ok : ((ki == 2) ? r2ok : true);
                bool cok = (kj == 0) ? c0ok : ((kj == 2) ? c2ok : true);
                int yy = ho - 1 + ki, xx = wo - 1 + kj;
                xv[ki * 3 + kj] = (rok && cok) ? xc[yy * 64 + xx] : 0.f;
            }
        }
#pragma unroll
        for (int kk = 0; kk < 9; kk++) {
            float xvk = xv[kk];
            const float4* wrow =
                reinterpret_cast<const float4*>(&ws[c * 252 + kk * 28]);
#pragma unroll
            for (int o4 = 0; o4 < 7; o4++) {
                float4 w = wrow[o4];
                acc[o4 * 4 + 0] += xvk * w.x;
                acc[o4 * 4 + 1] += xvk * w.y;
                acc[o4 * 4 + 2] += xvk * w.z;
                acc[o4 * 4 + 3] += xvk * w.w;
            }
        }
    }

#pragma unroll
    for (int i = 0; i < 27; i++)
        g_om8[((size_t)(sl * 27 + i)) * MTOT + m] = acc[i];
}

// ===========================================================================
// Kernel 2: offset finalize -> py / px / mask  (sums 8 slices)
// ===========================================================================
__global__ __launch_bounds__(256) void offset_final_kernel(
    const float* __restrict__ ob)
{
    const int m  = blockIdx.x * 256 + threadIdx.x;
    const int b  = m >> 12;
    const int p  = m & 4095;
    const int ho = p >> 6;
    const int wo = p & 63;

    float acc[27];
#pragma unroll
    for (int i = 0; i < 27; i++) {
        float s = 0.f;
#pragma unroll
        for (int sl = 0; sl < 8; sl++)
            s += g_om8[((size_t)(sl * 27 + i)) * MTOT + m];
        acc[i] = s;
    }

#pragma unroll
    for (int kk = 0; kk < 9; kk++) {
        float dy = acc[2 * kk]     + ob[2 * kk];
        float dx = acc[2 * kk + 1] + ob[2 * kk + 1];
        float mv = acc[18 + kk]    + ob[18 + kk];
        mv = 1.f / (1.f + __expf(-mv));
        int ki = kk / 3, kj = kk % 3;
        float pyv = dy + (float)(ho - 1 + ki);
        float pxv = dx + (float)(wo - 1 + kj);
        int o = ((b * 9 + kk) << 12) + p;
        g_py[o] = pyv;
        g_px[o] = pxv;
        g_pm[o] = mv;
    }
}

// ===========================================================================
// Kernel 3: bilinear gather -> A fp16, K-major g_Ah[k = c*9+kk][m]
//   c-split: blockIdx.z in {0,1}, 128 channels each
// ===========================================================================
__global__ __launch_bounds__(256) void gather_kernel(const float* __restrict__ x)
{
    const int tid = threadIdx.x;
    const int m   = blockIdx.x * 256 + tid;
    const int kk  = blockIdx.y;
    const int cs  = blockIdx.z * 128;
    const int b   = m >> 12;
    const int p   = m & 4095;

    const int o = ((b * 9 + kk) << 12) + p;
    const float pyv = g_py[o];
    const float pxv = g_px[o];
    const float mv  = g_pm[o];

    float y0f = floorf(pyv), x0f = floorf(pxv);
    float wy1 = pyv - y0f, wx1 = pxv - x0f;
    float wy0 = 1.f - wy1, wx0 = 1.f - wx1;
    int y0 = (int)y0f, x0 = (int)x0f;
    int y1 = y0 + 1,   x1 = x0 + 1;

    float w00 = wy0 * wx0 * mv, w01 = wy0 * wx1 * mv;
    float w10 = wy1 * wx0 * mv, w11 = wy1 * wx1 * mv;
    if (y0 < 0 || y0 > 63) { w00 = 0.f; w01 = 0.f; }
    if (y1 < 0 || y1 > 63) { w10 = 0.f; w11 = 0.f; }
    if (x0 < 0 || x0 > 63) { w00 = 0.f; w10 = 0.f; }
    if (x1 < 0 || x1 > 63) { w01 = 0.f; w11 = 0.f; }

    int y0c = min(max(y0, 0), 63), y1c = min(max(y1, 0), 63);
    int x0c = min(max(x0, 0), 63), x1c = min(max(x1, 0), 63);
    const int o00 = y0c * 64 + x0c, o01 = y0c * 64 + x1c;
    const int o10 = y1c * 64 + x0c, o11 = y1c * 64 + x1c;

    const float* xb = x + (size_t)(b * CIN + cs) * NPIX;
    const size_t base = (size_t)kk * MTOT + m + (size_t)cs * 9 * MTOT;

#pragma unroll 8
    for (int c = 0; c < 128; ++c) {
        const float* xc = xb + (size_t)c * NPIX;
        float v = w00 * xc[o00] + w01 * xc[o01] +
                  w10 * xc[o10] + w11 * xc[o11];
        g_Ah[base + (size_t)c * 9 * MTOT] = __float2half_rn(v);
    }
}

// ===========================================================================
// Kernel 4: HMMA GEMM  out[cout][m] = sum_k W[cout][k] * A[k][m]
//   Block tile 128 cout x 128 pixels, 8 warps (warp tile 64x32).
//   6-stage cp.async ring (BK=16, 10 KB/stage), one barrier per stage.
//   16 mma per warp per stage, single fp16 term.
//   Stage layout: [Ws 128 rows x 48B ([k0..7|k8..15|pad16]) | As 16x256 swz]
// ===========================================================================
#define NSTG      6
#define W_RS      48
#define STG_BYTES 10240
#define OFF_B     6144
#define GEMM_SMEM (NSTG * STG_BYTES)   // 61440

__global__ __launch_bounds__(256, 1) void gemm_kernel(
    const float* __restrict__ bias,
    float* __restrict__ out)
{
    extern __shared__ __align__(1024) unsigned char smem[];
    const uint32_t sbase = smem_u32(smem);
    const int tid  = threadIdx.x;
    const int warp = tid >> 5;
    const int lane = tid & 31;
    const int mBase    = blockIdx.x * 128;   // pixel base
    const int coutBase = blockIdx.y * 128;

    // ------ staging indices ------
    const int am = tid >> 1;          // W: cout row in tile 0..127
    const int ah = tid & 1;           // W: k half (8 fp16 = 16B)
    const int bk = tid >> 4;          // A: k row 0..15
    const int bc = tid & 15;          // A: pixel chunk (8 fp16)

    const char* gW = reinterpret_cast<const char*>(
        g_Wh + (size_t)(coutBase + am) * KDIM);
    const char* gB = reinterpret_cast<const char*>(
        g_Ah + (size_t)bk * MTOT + mBase + bc * 8);

    const uint32_t aSts = (uint32_t)(am * W_RS + ah * 16);
    const uint32_t bSts = (uint32_t)(bk * 256 + ((bc ^ (bk & 7)) * 16));

    // ------ fragment addresses ------
    const int wm = (warp >> 2) * 64;
    const int wn = (warp & 3) * 32;
    const uint32_t aAddrBase = sbase +
        (uint32_t)((wm + (lane & 15)) * W_RS + ((lane >> 4) & 1) * 16);
    const int kRow   = (lane & 7) + ((lane >> 3) & 1) * 8;
    const int chBase = (wn >> 3) + ((lane >> 4) & 1);
    const uint32_t bOff = (uint32_t)(kRow * 256);
    const uint32_t ch0 = (uint32_t)(((chBase + 0) ^ (kRow & 7)) * 16);
    const uint32_t ch1 = (uint32_t)(((chBase + 2) ^ (kRow & 7)) * 16);

    float acc[4][4][4];
#pragma unroll
    for (int i = 0; i < 4; i++)
#pragma unroll
        for (int j = 0; j < 4; j++)
#pragma unroll
            for (int r = 0; r < 4; r++) acc[i][j][r] = 0.f;

    const int NK = KDIM / 16;   // 144

    auto issue = [&](int kt, int buf) {
        const uint32_t sb = sbase + (uint32_t)(buf * STG_BYTES);
        cpasync16(sb + aSts,         gW + (size_t)kt * 32 + ah * 0 /*folded*/ );
        cpasync16(sb + OFF_B + bSts, gB + (size_t)kt * 16 * MTOT * 2);
        cp_commit();
    };
    // note: per-thread W source depends on ah; fold it into gW once:
    // thread loads 16B at row am, k-offset kt*32 + ah*16.
    // (gW already points at row am; adjust inside issue via ah)

    // redefine issue with correct ah offset (lambda above kept simple):
    auto issueW = [&](int kt, int buf) {
        const uint32_t sb = sbase + (uint32_t)(buf * STG_BYTES);
        cpasync16(sb + aSts,         gW + (size_t)kt * 32 + (size_t)ah * 16);
        cpasync16(sb + OFF_B + bSts, gB + (size_t)kt * 16 * MTOT * 2);
        cp_commit();
    };

#pragma unroll
    for (int kt = 0; kt < 5; ++kt) issueW(kt, kt);

    for (int kt = 0; kt < NK; ++kt) {
        const int buf = kt % NSTG;
        cp_wait4();
        __syncthreads();

        const uint32_t stg = (uint32_t)(buf * STG_BYTES);

        uint32_t wfr[4][4];
#pragma unroll
        for (int mi = 0; mi < 4; mi++) {
            uint32_t ad = aAddrBase + stg + (uint32_t)(mi * 16 * W_RS);
            ldsm_x4(wfr[mi][0], wfr[mi][1], wfr[mi][2], wfr[mi][3], ad);
        }
        uint32_t bfr[2][4];
        {
            const uint32_t hbase = sbase + OFF_B + stg + bOff;
            ldsm_x4_t(bfr[0][0], bfr[0][1], bfr[0][2], bfr[0][3], hbase + ch0);
            ldsm_x4_t(bfr[1][0], bfr[1][1], bfr[1][2], bfr[1][3], hbase + ch1);
        }

        if (kt + 5 < NK) issueW(kt + 5, (kt + 5) % NSTG);
        else             cp_commit();

        // ---- 16 mma, all independent accumulators ----
#pragma unroll
        for (int mi = 0; mi < 4; mi++)
#pragma unroll
            for (int nj = 0; nj < 2; nj++)
#pragma unroll
                for (int h = 0; h < 2; h++)
                    mma_f16(acc[mi][nj * 2 + h], wfr[mi],
                            bfr[nj][2 * h], bfr[nj][2 * h + 1]);

        __syncthreads();
    }

    // ---- epilogue ----
    const int g = lane >> 2;
    const int t = lane & 3;
    const int b    = mBase >> 12;
    const int pbB  = (mBase & 4095) + wn;
    float* outB = out + (size_t)b * COUT * NPIX;

#pragma unroll
    for (int mi = 0; mi < 4; mi++) {
        int c0 = coutBase + wm + mi * 16 + g;
        int c1 = c0 + 8;
        float bv0 = __ldg(&bias[c0]);
        float bv1 = __ldg(&bias[c1]);
        float* r0 = outB + (size_t)c0 * NPIX + pbB;
        float* r1 = outB + (size_t)c1 * NPIX + pbB;
#pragma unroll
        for (int ni = 0; ni < 4; ni++) {
            int pcol = ni * 8 + 2 * t;
            float2 v0 = make_float2(acc[mi][ni][0] + bv0, acc[mi][ni][1] + bv0);
            float2 v1 = make_float2(acc[mi][ni][2] + bv1, acc[mi][ni][3] + bv1);
            *reinterpret_cast<float2*>(r0 + pcol) = v0;
            *reinterpret_cast<float2*>(r1 + pcol) = v1;
        }
    }
}

// ===========================================================================
extern "C" void kernel_launch(void* const* d_in, const int* in_sizes, int n_in,
                              void* d_out, int out_size)
{
    const float* x        = (const float*)d_in[0];
    const float* weight   = (const float*)d_in[1];
    const float* bias     = (const float*)d_in[2];
    const float* offset_w = (const float*)d_in[3];
    const float* offset_b = (const float*)d_in[4];
    float* out = (float*)d_out;

    cudaFuncSetAttribute(gemm_kernel,
                         cudaFuncAttributeMaxDynamicSharedMemorySize, GEMM_SMEM);

    // 0) weight -> fp16
    wconv_kernel<<<(COUT * KDIM + 255) / 256, 256>>>(weight);

    // 1) offset conv partials (8 channel slices of 32)
    dim3 ogrid(MTOT / 256, 8);
    offset_partial_kernel<<<ogrid, 256>>>(x, offset_w);

    // 2) finalize offsets
    offset_final_kernel<<<MTOT / 256, 256>>>(offset_b);

    // 3) bilinear gather -> fp16 A matrix (c-split x2)
    dim3 ggrid(MTOT / 256, KKN, 2);
    gather_kernel<<<ggrid, 256>>>(x);

    // 4) HMMA GEMM + bias (cp.async pipelined, single fp16 term)
    dim3 mgrid(MTOT / 128, COUT / 128);
    gemm_kernel<<<mgrid, 256, GEMM_SMEM>>>(bias, out);
}